// round 9
// baseline (speedup 1.0000x reference)
#include <cuda_runtime.h>
#include <cuda_bf16.h>
#include <stdint.h>
#include <math.h>

#define N_NODES 50000
#define N_EDGES 800000
#define C_IN    768
#define C1      256
#define C2      128
#define C3      2

#define SCAN_T  1024
#define SCAN_CH ((N_NODES + SCAN_T - 1) / SCAN_T)   // 49

// ---------------- scratch (device globals; no allocation allowed) ----------
__device__ float g_dinv[N_NODES];
__device__ int   g_cnt[N_NODES];            // counts, then write cursor
__device__ int   g_off[N_NODES + 1];
__device__ int   g_csr[N_EDGES];            // src ids grouped by dst
__device__ __nv_bfloat16 g_h1[(size_t)N_NODES * C1];
__device__ float g_a1[(size_t)N_NODES * C1];
__device__ __nv_bfloat16 g_h2[(size_t)N_NODES * C2];
__device__ float g_a2[(size_t)N_NODES * C2];
__device__ float g_h3[(size_t)N_NODES * C3];

// ---------------- CSR build -------------------------------------------------
__global__ void k_zero_cnt() {
    int i = blockIdx.x * blockDim.x + threadIdx.x;
    if (i < N_NODES) g_cnt[i] = 0;
}

__global__ void k_count(const int* __restrict__ dst) {
    int e = blockIdx.x * blockDim.x + threadIdx.x;
    if (e < N_EDGES) atomicAdd(&g_cnt[dst[e]], 1);
}

// single block: exclusive scan of counts -> g_off, dinv, and leave cursor in g_cnt
__global__ void __launch_bounds__(SCAN_T) k_scan() {
    __shared__ int s_part[SCAN_T];
    const int t = threadIdx.x;
    const int start = t * SCAN_CH;
    const int end   = min(start + SCAN_CH, N_NODES);

    int sum = 0;
    for (int i = start; i < end; i++) {
        int c = g_cnt[i];
        sum += c;
        g_dinv[i] = rsqrtf((float)(c + 1));   // +1 self loop
    }
    s_part[t] = sum;
    __syncthreads();
    for (int ofs = 1; ofs < SCAN_T; ofs <<= 1) {
        int v = 0;
        if (t >= ofs) v = s_part[t - ofs];
        __syncthreads();
        if (t >= ofs) s_part[t] += v;
        __syncthreads();
    }
    int run = (t == 0) ? 0 : s_part[t - 1];
    for (int i = start; i < end; i++) {
        int c = g_cnt[i];
        g_off[i] = run;
        g_cnt[i] = run;       // write cursor for k_fill
        run += c;
    }
    if (start < N_NODES && end == N_NODES) g_off[N_NODES] = run;
}

__global__ void k_fill(const int* __restrict__ src, const int* __restrict__ dst) {
    int e = blockIdx.x * blockDim.x + threadIdx.x;
    if (e < N_EDGES) {
        int pos = atomicAdd(&g_cnt[dst[e]], 1);
        g_csr[pos] = src[e];
    }
}

// ---------------- TF32 tensor-core GEMM, 4-stage cp.async -------------------
#define AST 20
#define BST 136
#define AS_WORDS (128 * AST)   // 2560
#define BS_WORDS (16 * BST)    // 2176
#define NSTAGE 4
#define GEMM_SMEM ((NSTAGE * AS_WORDS + NSTAGE * BS_WORDS) * 4)   // 75776 B

__device__ __forceinline__ void cp16(unsigned int dst, const void* src, bool pred) {
    asm volatile("cp.async.cg.shared.global [%0], [%1], 16, %2;"
                 :: "r"(dst), "l"(src), "r"(pred ? 16 : 0));
}

template <bool OUT_BF16>
__global__ void __launch_bounds__(256) tf32_gemm(const float* __restrict__ A,
                                                 const float* __restrict__ B,
                                                 void* __restrict__ Cout,
                                                 int M, int K, int N) {
    extern __shared__ float sm[];
    const int tid  = threadIdx.x;
    const int warp = tid >> 5;
    const int lane = tid & 31;
    const int gid  = lane >> 2;
    const int tig  = lane & 3;
    const int wm   = warp & 1;
    const int wn   = warp >> 1;
    const int bm   = blockIdx.y * 128;
    const int bn   = blockIdx.x * 128;

    unsigned int sbase;
    asm("{ .reg .u64 t; cvta.to.shared.u64 t, %1; cvt.u32.u64 %0, t; }"
        : "=r"(sbase) : "l"(sm));

    float acc[4][4][4];
#pragma unroll
    for (int i = 0; i < 4; i++)
#pragma unroll
        for (int j = 0; j < 4; j++)
#pragma unroll
            for (int q = 0; q < 4; q++) acc[i][j][q] = 0.0f;

    const int nIter = K / 16;

    auto issue = [&](int stage, int k0) {
        unsigned int aB = sbase + (unsigned int)stage * AS_WORDS * 4;
        unsigned int bB = sbase + (unsigned int)(NSTAGE * AS_WORDS + stage * BS_WORDS) * 4;
        {
            int c = tid, r = c >> 2, kc = c & 3;
            cp16(aB + (unsigned int)(r * AST + kc * 4) * 4,
                 A + (size_t)(bm + r) * K + k0 + kc * 4, (bm + r) < M);
        }
        {
            int c = tid + 256, r = c >> 2, kc = c & 3;
            cp16(aB + (unsigned int)(r * AST + kc * 4) * 4,
                 A + (size_t)(bm + r) * K + k0 + kc * 4, (bm + r) < M);
        }
        {
            int c = tid, r = c >> 5, n4 = c & 31;
            cp16(bB + (unsigned int)(r * BST + n4 * 4) * 4,
                 B + (size_t)(k0 + r) * N + bn + n4 * 4, true);
        }
        {
            int c = tid + 256, r = c >> 5, n4 = c & 31;
            cp16(bB + (unsigned int)(r * BST + n4 * 4) * 4,
                 B + (size_t)(k0 + r) * N + bn + n4 * 4, true);
        }
        asm volatile("cp.async.commit_group;");
    };

    issue(0, 0);
    if (nIter > 1) issue(1, 16);
    if (nIter > 2) issue(2, 32);

    for (int it = 0; it < nIter; it++) {
        asm volatile("cp.async.wait_group 2;");
        __syncthreads();

        if (it + 3 < nIter) issue((it + 3) % NSTAGE, (it + 3) * 16);

        const int stage = it % NSTAGE;
        const float* Asb = sm + stage * AS_WORDS;
        const float* Bsb = sm + NSTAGE * AS_WORDS + stage * BS_WORDS;

#pragma unroll
        for (int ks = 0; ks < 2; ks++) {
            int kk = ks * 8;
            unsigned af[4][4], bf[4][2];
#pragma unroll
            for (int im = 0; im < 4; im++) {
                int m = wm * 64 + im * 16 + gid;
                af[im][0] = __float_as_uint(Asb[m * AST + kk + tig]);
                af[im][1] = __float_as_uint(Asb[(m + 8) * AST + kk + tig]);
                af[im][2] = __float_as_uint(Asb[m * AST + kk + tig + 4]);
                af[im][3] = __float_as_uint(Asb[(m + 8) * AST + kk + tig + 4]);
            }
#pragma unroll
            for (int in_ = 0; in_ < 4; in_++) {
                int n = wn * 32 + in_ * 8 + gid;
                bf[in_][0] = __float_as_uint(Bsb[(kk + tig) * BST + n]);
                bf[in_][1] = __float_as_uint(Bsb[(kk + tig + 4) * BST + n]);
            }
#pragma unroll
            for (int im = 0; im < 4; im++)
#pragma unroll
                for (int in_ = 0; in_ < 4; in_++) {
                    asm volatile(
                        "mma.sync.aligned.m16n8k8.row.col.f32.tf32.tf32.f32 "
                        "{%0,%1,%2,%3}, {%4,%5,%6,%7}, {%8,%9}, {%0,%1,%2,%3};"
                        : "+f"(acc[im][in_][0]), "+f"(acc[im][in_][1]),
                          "+f"(acc[im][in_][2]), "+f"(acc[im][in_][3])
                        : "r"(af[im][0]), "r"(af[im][1]),
                          "r"(af[im][2]), "r"(af[im][3]),
                          "r"(bf[in_][0]), "r"(bf[in_][1]));
                }
        }
    }

#pragma unroll
    for (int im = 0; im < 4; im++) {
        int r0 = bm + wm * 64 + im * 16 + gid;
        int r1 = r0 + 8;
#pragma unroll
        for (int in_ = 0; in_ < 4; in_++) {
            int c = bn + wn * 32 + in_ * 8 + 2 * tig;
            if (OUT_BF16) {
                __nv_bfloat16* ob = (__nv_bfloat16*)Cout;
                if (r0 < M)
                    *(__nv_bfloat162*)(ob + (size_t)r0 * N + c) =
                        __floats2bfloat162_rn(acc[im][in_][0], acc[im][in_][1]);
                if (r1 < M)
                    *(__nv_bfloat162*)(ob + (size_t)r1 * N + c) =
                        __floats2bfloat162_rn(acc[im][in_][2], acc[im][in_][3]);
            } else {
                float* of = (float*)Cout;
                if (r0 < M)
                    *(float2*)(of + (size_t)r0 * N + c) =
                        make_float2(acc[im][in_][0], acc[im][in_][1]);
                if (r1 < M)
                    *(float2*)(of + (size_t)r1 * N + c) =
                        make_float2(acc[im][in_][2], acc[im][in_][3]);
            }
        }
    }
}

// ---------------- CSR gather aggregation (bf16 in, fp32 out) ----------------
__global__ void __launch_bounds__(256) k_gather256(const __nv_bfloat16* __restrict__ h,
                                                   const float* __restrict__ bias,
                                                   float* __restrict__ out) {
    const int node = (blockIdx.x * blockDim.x + threadIdx.x) >> 5;
    const int lane = threadIdx.x & 31;
    if (node >= N_NODES) return;

    float acc[8];
#pragma unroll
    for (int i = 0; i < 8; i++) acc[i] = 0.f;

    const int e0 = g_off[node];
    const int e1 = g_off[node + 1];
    for (int e = e0; e < e1; e++) {
        int s = g_csr[e];
        float w = g_dinv[s];
        uint4 q = ((const uint4*)(h + (size_t)s * C1))[lane];
        float2 f0 = __bfloat1622float2(*(__nv_bfloat162*)&q.x);
        float2 f1 = __bfloat1622float2(*(__nv_bfloat162*)&q.y);
        float2 f2 = __bfloat1622float2(*(__nv_bfloat162*)&q.z);
        float2 f3 = __bfloat1622float2(*(__nv_bfloat162*)&q.w);
        acc[0] += f0.x * w; acc[1] += f0.y * w;
        acc[2] += f1.x * w; acc[3] += f1.y * w;
        acc[4] += f2.x * w; acc[5] += f2.y * w;
        acc[6] += f3.x * w; acc[7] += f3.y * w;
    }

    float dd = g_dinv[node];
    uint4 q = ((const uint4*)(h + (size_t)node * C1))[lane];
    float2 f0 = __bfloat1622float2(*(__nv_bfloat162*)&q.x);
    float2 f1 = __bfloat1622float2(*(__nv_bfloat162*)&q.y);
    float2 f2 = __bfloat1622float2(*(__nv_bfloat162*)&q.z);
    float2 f3 = __bfloat1622float2(*(__nv_bfloat162*)&q.w);
    float sf[8] = {f0.x, f0.y, f1.x, f1.y, f2.x, f2.y, f3.x, f3.y};

    float4 b0 = ((const float4*)bias)[lane * 2 + 0];
    float4 b1 = ((const float4*)bias)[lane * 2 + 1];
    float bb[8] = {b0.x, b0.y, b0.z, b0.w, b1.x, b1.y, b1.z, b1.w};

    float r[8];
#pragma unroll
    for (int i = 0; i < 8; i++)
        r[i] = fmaxf((acc[i] + sf[i] * dd) * dd + bb[i], 0.f);

    float4* on = (float4*)(out + (size_t)node * C1 + lane * 8);
    on[0] = make_float4(r[0], r[1], r[2], r[3]);
    on[1] = make_float4(r[4], r[5], r[6], r[7]);
}

__global__ void __launch_bounds__(256) k_gather128(const __nv_bfloat16* __restrict__ h,
                                                   const float* __restrict__ bias,
                                                   float* __restrict__ out) {
    const int node = (blockIdx.x * blockDim.x + threadIdx.x) >> 5;
    const int lane = threadIdx.x & 31;
    if (node >= N_NODES) return;

    float acc[4] = {0.f, 0.f, 0.f, 0.f};

    const int e0 = g_off[node];
    const int e1 = g_off[node + 1];
    for (int e = e0; e < e1; e++) {
        int s = g_csr[e];
        float w = g_dinv[s];
        uint2 q = ((const uint2*)(h + (size_t)s * C2))[lane];
        float2 f0 = __bfloat1622float2(*(__nv_bfloat162*)&q.x);
        float2 f1 = __bfloat1622float2(*(__nv_bfloat162*)&q.y);
        acc[0] += f0.x * w; acc[1] += f0.y * w;
        acc[2] += f1.x * w; acc[3] += f1.y * w;
    }

    float dd = g_dinv[node];
    uint2 q = ((const uint2*)(h + (size_t)node * C2))[lane];
    float2 f0 = __bfloat1622float2(*(__nv_bfloat162*)&q.x);
    float2 f1 = __bfloat1622float2(*(__nv_bfloat162*)&q.y);
    float sf[4] = {f0.x, f0.y, f1.x, f1.y};

    float4 b = ((const float4*)bias)[lane];
    float bb[4] = {b.x, b.y, b.z, b.w};

    float r[4];
#pragma unroll
    for (int i = 0; i < 4; i++)
        r[i] = fmaxf((acc[i] + sf[i] * dd) * dd + bb[i], 0.f);

    *(float4*)(out + (size_t)node * C2 + lane * 4) = make_float4(r[0], r[1], r[2], r[3]);
}

__global__ void __launch_bounds__(256) k_gather2_sig(const float* __restrict__ h,
                                                     const float* __restrict__ bias,
                                                     float* __restrict__ out) {
    const int node = (blockIdx.x * blockDim.x + threadIdx.x) >> 5;
    const int lane = threadIdx.x & 31;
    if (node >= N_NODES) return;

    float a0 = 0.f, a1 = 0.f;
    const int e0 = g_off[node];
    const int e1 = g_off[node + 1];
    for (int e = e0 + lane; e < e1; e += 32) {
        int s = g_csr[e];
        float w = g_dinv[s];
        float2 f = ((const float2*)h)[s];
        a0 += f.x * w;
        a1 += f.y * w;
    }
#pragma unroll
    for (int o = 16; o > 0; o >>= 1) {
        a0 += __shfl_down_sync(0xffffffffu, a0, o);
        a1 += __shfl_down_sync(0xffffffffu, a1, o);
    }
    if (lane == 0) {
        float dd = g_dinv[node];
        float2 f = ((const float2*)h)[node];
        float r0 = (a0 + f.x * dd) * dd + bias[0];
        float r1 = (a1 + f.y * dd) * dd + bias[1];
        float2 o2;
        o2.x = 1.0f / (1.0f + expf(-r0));
        o2.y = 1.0f / (1.0f + expf(-r1));
        ((float2*)out)[node] = o2;
    }
}

// ---------------- layer-3 GEMM (K=128 -> 2 outputs), warp per row ----------
__global__ void k_gemm3(const float* __restrict__ A, const float* __restrict__ W,
                        float* __restrict__ out) {
    int warp = (blockIdx.x * blockDim.x + threadIdx.x) >> 5;
    int lane = threadIdx.x & 31;
    if (warp >= N_NODES) return;
    const float* ar = A + (size_t)warp * C2;
    float a0 = 0.0f, a1 = 0.0f;
#pragma unroll
    for (int k = lane; k < C2; k += 32) {
        float v = ar[k];
        a0 += v * W[k * 2 + 0];
        a1 += v * W[k * 2 + 1];
    }
#pragma unroll
    for (int o = 16; o > 0; o >>= 1) {
        a0 += __shfl_down_sync(0xffffffffu, a0, o);
        a1 += __shfl_down_sync(0xffffffffu, a1, o);
    }
    if (lane == 0) {
        out[(size_t)warp * 2 + 0] = a0;
        out[(size_t)warp * 2 + 1] = a1;
    }
}

// ---------------- launch ----------------------------------------------------
extern "C" void kernel_launch(void* const* d_in, const int* in_sizes, int n_in,
                              void* d_out, int out_size) {
    const float* x  = (const float*)d_in[0];
    const int*   ei = (const int*)d_in[1];
    const float* W1 = (const float*)d_in[2];
    const float* b1 = (const float*)d_in[3];
    const float* W2 = (const float*)d_in[4];
    const float* b2 = (const float*)d_in[5];
    const float* W3 = (const float*)d_in[6];
    const float* b3 = (const float*)d_in[7];
    float* out = (float*)d_out;

    const int* src = ei;
    const int* dst = ei + N_EDGES;

    __nv_bfloat16* h1; cudaGetSymbolAddress((void**)&h1, g_h1);
    float* a1;         cudaGetSymbolAddress((void**)&a1, g_a1);
    __nv_bfloat16* h2; cudaGetSymbolAddress((void**)&h2, g_h2);
    float* a2;         cudaGetSymbolAddress((void**)&a2, g_a2);
    float* h3;         cudaGetSymbolAddress((void**)&h3, g_h3);

    // one-time host resources (created on the uncaptured correctness call)
    static cudaStream_t s2 = nullptr;
    static cudaEvent_t ev_fork = nullptr, ev_join = nullptr;
    static bool init_done = false;
    if (!init_done) {
        cudaStreamCreateWithFlags(&s2, cudaStreamNonBlocking);
        cudaEventCreateWithFlags(&ev_fork, cudaEventDisableTiming);
        cudaEventCreateWithFlags(&ev_join, cudaEventDisableTiming);
        cudaFuncSetAttribute(tf32_gemm<true>,
                             cudaFuncAttributeMaxDynamicSharedMemorySize, GEMM_SMEM);
        init_done = true;
    }

    const int T = 256;

    // ---- fork: CSR build on s2, GEMM1 on main stream (independent)
    cudaEventRecord(ev_fork, 0);
    cudaStreamWaitEvent(s2, ev_fork, 0);

    k_zero_cnt<<<(N_NODES + T - 1) / T, T, 0, s2>>>();
    k_count<<<(N_EDGES + T - 1) / T, T, 0, s2>>>(dst);
    k_scan<<<1, SCAN_T, 0, s2>>>();
    k_fill<<<(N_EDGES + T - 1) / T, T, 0, s2>>>(src, dst);
    cudaEventRecord(ev_join, s2);

    {
        dim3 grid(C1 / 128, (N_NODES + 127) / 128);
        tf32_gemm<true><<<grid, 256, GEMM_SMEM>>>(x, W1, h1, N_NODES, C_IN, C1);
    }

    // ---- join: everything below needs both CSR and h1
    cudaStreamWaitEvent(0, ev_join, 0);

    k_gather256<<<(N_NODES * 32 + T - 1) / T, T>>>(h1, b1, a1);

    // ---- layer 2
    {
        dim3 grid(C2 / 128, (N_NODES + 127) / 128);
        tf32_gemm<true><<<grid, 256, GEMM_SMEM>>>(a1, W2, h2, N_NODES, C1, C2);
    }
    k_gather128<<<(N_NODES * 32 + T - 1) / T, T>>>(h2, b2, a2);

    // ---- layer 3
    k_gemm3<<<(N_NODES * 32 + T - 1) / T, T>>>(a2, W3, h3);
    k_gather2_sig<<<(N_NODES * 32 + T - 1) / T, T>>>(h3, b3, out);
}